// round 2
// baseline (speedup 1.0000x reference)
#include <cuda_runtime.h>
#include <cstdint>

#define B_  4
#define N_  2048
#define C_  768
#define H_  12
#define D_  64
#define C3_ 2304
#define M_  (B_ * N_)   // 8192

// Scratch (device globals — no allocation allowed in kernel_launch)
__device__ float g_qkv[(size_t)M_ * C3_];   // [B*N, 3C]
__device__ float g_att[(size_t)M_ * C_];    // [B*N, C]
__device__ float g_maskbias[M_];            // 0 or -1e30 per (b, key)

// ---------------------------------------------------------------------------
// Mask expansion, robust to bool-as-int8 or bool-as-int32 serialization.
// Scans the first 2048 32-bit words (valid region under BOTH layouts: byte
// storage has exactly 2048 words; int32 storage has 8192). If any word > 1,
// the buffer is byte-packed (random 0/1 bytes give a word>1 with prob 7/8
// per word, so detection is certain); otherwise it is int32 0/1 values.
// ---------------------------------------------------------------------------
__global__ void expand_mask_kernel(const void* __restrict__ pm)
{
    __shared__ int s_byte_mode;
    if (threadIdx.x == 0) s_byte_mode = 0;
    __syncthreads();

    const unsigned* w = (const unsigned*)pm;
    for (int i = threadIdx.x; i < 2048; i += blockDim.x) {
        if (w[i] > 1u) s_byte_mode = 1;   // benign race: same value
    }
    __syncthreads();
    const int byte_mode = s_byte_mode;

    const uint8_t* p8  = (const uint8_t*)pm;
    const int*     p32 = (const int*)pm;
    for (int i = threadIdx.x; i < M_; i += blockDim.x) {
        int m = byte_mode ? (int)p8[i] : p32[i];
        g_maskbias[i] = m ? -1e30f : 0.0f;
    }
}

// ---------------------------------------------------------------------------
// SGEMM: Cout[M,Nc] = A[M,K] @ W[K,Nc] + bias   (all row-major, dims % tile == 0)
// 128x128 block tile, BK=16, 256 threads, 8x8 micro-tile, A stored transposed
// in smem so both operands are read as float4 along the contiguous dim.
// ---------------------------------------------------------------------------
template<int BM, int BN, int BK>
__global__ __launch_bounds__(256)
void sgemm_bias(const float* __restrict__ A, const float* __restrict__ W,
                const float* __restrict__ bias, float* __restrict__ Cout,
                int M, int K, int Nc)
{
    __shared__ float As[BK][BM];   // transposed: As[k][m]
    __shared__ float Ws[BK][BN];
    const int tid = threadIdx.x;
    const int tx = tid & 15;       // col group (8 cols each)
    const int ty = tid >> 4;       // row group (8 rows each)
    const int bm = blockIdx.y * BM;
    const int bn = blockIdx.x * BN;

    float acc[8][8];
    #pragma unroll
    for (int i = 0; i < 8; i++)
        #pragma unroll
        for (int j = 0; j < 8; j++) acc[i][j] = 0.f;

    for (int k0 = 0; k0 < K; k0 += BK) {
        // Load A tile (BM x BK) -> As transposed. 2 float4 per thread.
        #pragma unroll
        for (int i = 0; i < (BM * BK) / (256 * 4); i++) {
            int f = tid + i * 256;
            int r = f >> 2;            // 0..127
            int c = (f & 3) << 2;      // 0,4,8,12
            float4 v = *(const float4*)(A + (size_t)(bm + r) * K + k0 + c);
            As[c + 0][r] = v.x; As[c + 1][r] = v.y;
            As[c + 2][r] = v.z; As[c + 3][r] = v.w;
        }
        // Load W tile (BK x BN). 2 float4 per thread.
        #pragma unroll
        for (int i = 0; i < (BK * BN) / (256 * 4); i++) {
            int f = tid + i * 256;
            int r = f >> 5;            // 0..15
            int c = (f & 31) << 2;     // 0..124
            *(float4*)(&Ws[r][c]) = *(const float4*)(W + (size_t)(k0 + r) * Nc + bn + c);
        }
        __syncthreads();

        #pragma unroll
        for (int k = 0; k < BK; k++) {
            float4 a0 = *(const float4*)(&As[k][ty * 8]);
            float4 a1 = *(const float4*)(&As[k][ty * 8 + 4]);
            float4 b0 = *(const float4*)(&Ws[k][tx * 8]);
            float4 b1 = *(const float4*)(&Ws[k][tx * 8 + 4]);
            float av[8] = {a0.x, a0.y, a0.z, a0.w, a1.x, a1.y, a1.z, a1.w};
            float bv[8] = {b0.x, b0.y, b0.z, b0.w, b1.x, b1.y, b1.z, b1.w};
            #pragma unroll
            for (int i = 0; i < 8; i++)
                #pragma unroll
                for (int j = 0; j < 8; j++) acc[i][j] += av[i] * bv[j];
        }
        __syncthreads();
    }

    #pragma unroll
    for (int i = 0; i < 8; i++) {
        size_t r = (size_t)(bm + ty * 8 + i);
        #pragma unroll
        for (int j = 0; j < 8; j += 4) {
            int cc = bn + tx * 8 + j;
            float4 o;
            o.x = acc[i][j + 0] + bias[cc + 0];
            o.y = acc[i][j + 1] + bias[cc + 1];
            o.z = acc[i][j + 2] + bias[cc + 2];
            o.w = acc[i][j + 3] + bias[cc + 3];
            *(float4*)(Cout + r * Nc + cc) = o;
        }
    }
}

// ---------------------------------------------------------------------------
// Flash attention: per (b, h, 64-row q tile), stream 64-key tiles.
// 128 threads; thread (ty in [0,16), tx in [0,8)) owns a 4x8 micro-tile.
// smem: Qt[64][64] (Q transposed: [d][q]), SB[64][68] (K transposed [d][k],
// reused as P[q][k]), Vs[64][64] ([k][d]). Pitch 68 kills transpose-write /
// P-read bank conflicts while keeping 16B alignment for float4 K reads.
// Online softmax with alibi bias + padding mask bias (-1e30 == -inf after exp).
// ---------------------------------------------------------------------------
__global__ __launch_bounds__(128)
void flash_kernel(const float* __restrict__ qkv,
                  const float* __restrict__ alibi,
                  float* __restrict__ outp)
{
    extern __shared__ float sm[];
    float* Qt = sm;                // 64*64
    float* SB = sm + 64 * 64;      // 64*68  (Kt, then P)
    float* Vs = SB + 64 * 68;      // 64*64

    const int q0 = blockIdx.x * 64;
    const int h  = blockIdx.y;
    const int b  = blockIdx.z;
    const int tid = threadIdx.x;
    const int tx = tid & 7;        // col group (8 cols)
    const int ty = tid >> 3;       // row group (4 rows), 0..15
    const float scale = 0.125f;    // 1/sqrt(64)

    const size_t qbase = (size_t)b * N_ * C3_ + (size_t)h * D_;

    // Load+transpose Q tile: Qt[d][q]
    #pragma unroll
    for (int i = 0; i < 8; i++) {
        int f = tid + i * 128;
        int r = f >> 4;            // q row 0..63
        int c = (f & 15) << 2;     // d 0,4,..60
        float4 v = *(const float4*)(qkv + qbase + (size_t)(q0 + r) * C3_ + c);
        Qt[(c + 0) * 64 + r] = v.x;
        Qt[(c + 1) * 64 + r] = v.y;
        Qt[(c + 2) * 64 + r] = v.z;
        Qt[(c + 3) * 64 + r] = v.w;
    }

    float o[4][8];
    #pragma unroll
    for (int i = 0; i < 4; i++)
        #pragma unroll
        for (int j = 0; j < 8; j++) o[i][j] = 0.f;
    float mr[4] = {-1e30f, -1e30f, -1e30f, -1e30f};
    float lr[4] = {0.f, 0.f, 0.f, 0.f};

    const float* abase = alibi + ((size_t)(b * H_ + h) * N_ + q0) * N_;

    for (int kt = 0; kt < N_ / 64; kt++) {
        const int k0 = kt * 64;
        __syncthreads();   // previous P / V fully consumed (and Qt ready on iter 0)

        // Load K tile transposed into SB[d][k] (pitch 68), V tile into Vs[k][d]
        #pragma unroll
        for (int i = 0; i < 8; i++) {
            int f = tid + i * 128;
            int r = f >> 4;            // key 0..63
            int c = (f & 15) << 2;     // d
            const float* kp = qkv + qbase + C_ + (size_t)(k0 + r) * C3_ + c;
            float4 kv = *(const float4*)kp;
            SB[(c + 0) * 68 + r] = kv.x;
            SB[(c + 1) * 68 + r] = kv.y;
            SB[(c + 2) * 68 + r] = kv.z;
            SB[(c + 3) * 68 + r] = kv.w;
            *(float4*)(Vs + r * 64 + c) = *(const float4*)(kp + C_);
        }
        __syncthreads();

        // S = Q @ K^T (4x8 per thread)
        float s[4][8];
        #pragma unroll
        for (int i = 0; i < 4; i++)
            #pragma unroll
            for (int j = 0; j < 8; j++) s[i][j] = 0.f;

        #pragma unroll 8
        for (int k = 0; k < 64; k++) {
            float4 a  = *(const float4*)(Qt + k * 64 + ty * 4);
            float4 b0 = *(const float4*)(SB + k * 68 + tx * 8);
            float4 b1 = *(const float4*)(SB + k * 68 + tx * 8 + 4);
            float av[4] = {a.x, a.y, a.z, a.w};
            float bv[8] = {b0.x, b0.y, b0.z, b0.w, b1.x, b1.y, b1.z, b1.w};
            #pragma unroll
            for (int i = 0; i < 4; i++)
                #pragma unroll
                for (int j = 0; j < 8; j++) s[i][j] += av[i] * bv[j];
        }

        // scale + alibi + padding-mask bias
        const float* mbp = g_maskbias + (size_t)b * N_ + k0 + tx * 8;
        float4 m0 = *(const float4*)mbp;
        float4 m1 = *(const float4*)(mbp + 4);
        float mb[8] = {m0.x, m0.y, m0.z, m0.w, m1.x, m1.y, m1.z, m1.w};

        #pragma unroll
        for (int i = 0; i < 4; i++) {
            const float* ap = abase + (size_t)(ty * 4 + i) * N_ + k0 + tx * 8;
            float4 a0 = *(const float4*)ap;
            float4 a1 = *(const float4*)(ap + 4);
            float al[8] = {a0.x, a0.y, a0.z, a0.w, a1.x, a1.y, a1.z, a1.w};
            #pragma unroll
            for (int j = 0; j < 8; j++)
                s[i][j] = s[i][j] * scale + al[j] + mb[j];
        }

        // online softmax (row stats across the 8 lanes sharing a row group)
        #pragma unroll
        for (int i = 0; i < 4; i++) {
            float mx = s[i][0];
            #pragma unroll
            for (int j = 1; j < 8; j++) mx = fmaxf(mx, s[i][j]);
            mx = fmaxf(mx, __shfl_xor_sync(0xffffffffu, mx, 4));
            mx = fmaxf(mx, __shfl_xor_sync(0xffffffffu, mx, 2));
            mx = fmaxf(mx, __shfl_xor_sync(0xffffffffu, mx, 1));
            float mn  = fmaxf(mr[i], mx);
            float fct = __expf(mr[i] - mn);
            mr[i] = mn;
            float rs = 0.f;
            #pragma unroll
            for (int j = 0; j < 8; j++) {
                float p = __expf(s[i][j] - mn);
                s[i][j] = p;
                rs += p;
            }
            rs += __shfl_xor_sync(0xffffffffu, rs, 4);
            rs += __shfl_xor_sync(0xffffffffu, rs, 2);
            rs += __shfl_xor_sync(0xffffffffu, rs, 1);
            lr[i] = lr[i] * fct + rs;
            #pragma unroll
            for (int j = 0; j < 8; j++) o[i][j] *= fct;
        }

        __syncthreads();   // everyone done reading Kt before P overwrites SB
        #pragma unroll
        for (int i = 0; i < 4; i++)
            #pragma unroll
            for (int j = 0; j < 8; j++)
                SB[(ty * 4 + i) * 68 + tx * 8 + j] = s[i][j];
        __syncthreads();

        // O += P @ V
        #pragma unroll 8
        for (int kk = 0; kk < 64; kk++) {
            float p0 = SB[(ty * 4 + 0) * 68 + kk];
            float p1 = SB[(ty * 4 + 1) * 68 + kk];
            float p2 = SB[(ty * 4 + 2) * 68 + kk];
            float p3 = SB[(ty * 4 + 3) * 68 + kk];
            float4 v0 = *(const float4*)(Vs + kk * 64 + tx * 8);
            float4 v1 = *(const float4*)(Vs + kk * 64 + tx * 8 + 4);
            float vv[8] = {v0.x, v0.y, v0.z, v0.w, v1.x, v1.y, v1.z, v1.w};
            #pragma unroll
            for (int j = 0; j < 8; j++) {
                o[0][j] += p0 * vv[j];
                o[1][j] += p1 * vv[j];
                o[2][j] += p2 * vv[j];
                o[3][j] += p3 * vv[j];
            }
        }
    }

    // epilogue: normalize and write to [B*N, C] at column h*64
    #pragma unroll
    for (int i = 0; i < 4; i++) {
        float inv = 1.0f / lr[i];
        size_t r = (size_t)b * N_ + q0 + ty * 4 + i;
        float* op = outp + r * C_ + h * D_ + tx * 8;
        float4 w0, w1;
        w0.x = o[i][0] * inv; w0.y = o[i][1] * inv;
        w0.z = o[i][2] * inv; w0.w = o[i][3] * inv;
        w1.x = o[i][4] * inv; w1.y = o[i][5] * inv;
        w1.z = o[i][6] * inv; w1.w = o[i][7] * inv;
        *(float4*)op       = w0;
        *(float4*)(op + 4) = w1;
    }
}

// ---------------------------------------------------------------------------
extern "C" void kernel_launch(void* const* d_in, const int* in_sizes, int n_in,
                              void* d_out, int out_size)
{
    const float* x      = (const float*)d_in[0];
    const void*  pm     = d_in[1];
    const float* alibi  = (const float*)d_in[2];
    const float* qkv_w  = (const float*)d_in[3];
    const float* qkv_b  = (const float*)d_in[4];
    const float* proj_w = (const float*)d_in[5];
    const float* proj_b = (const float*)d_in[6];
    float* out = (float*)d_out;

    float *qkv, *att;
    cudaGetSymbolAddress((void**)&qkv, g_qkv);
    cudaGetSymbolAddress((void**)&att, g_att);

    const int FLASH_SMEM = (64 * 64 + 64 * 68 + 64 * 64) * (int)sizeof(float); // 50176
    cudaFuncSetAttribute(flash_kernel,
                         cudaFuncAttributeMaxDynamicSharedMemorySize, FLASH_SMEM);

    // 0) expand padding mask (dtype-robust) -> g_maskbias
    expand_mask_kernel<<<1, 1024>>>(pm);

    // 1) qkv = x @ qkv_w + qkv_b           [8192, 2304]
    sgemm_bias<128, 128, 16><<<dim3(C3_ / 128, M_ / 128), 256>>>(
        x, qkv_w, qkv_b, qkv, M_, C_, C3_);

    // 2) flash attention (alibi + padding mask + softmax + @V)  -> g_att
    flash_kernel<<<dim3(N_ / 64, H_, B_), 128, FLASH_SMEM>>>(qkv, alibi, att);

    // 3) out = att @ proj_w + proj_b       [8192, 768]
    sgemm_bias<128, 128, 16><<<dim3(C_ / 128, M_ / 128), 256>>>(
        att, proj_w, proj_b, out, M_, C_, C_);
}

// round 3
// speedup vs baseline: 2.9559x; 2.9559x over previous
#include <cuda_runtime.h>
#include <cstdint>

#define B_  4
#define N_  2048
#define C_  768
#define H_  12
#define D_  64
#define C3_ 2304
#define M_  (B_ * N_)   // 8192

// Scratch (device globals — no allocation allowed in kernel_launch)
__device__ float g_qkv[(size_t)M_ * C3_];   // [B*N, 3C]
__device__ float g_att[(size_t)M_ * C_];    // [B*N, C]
__device__ float g_maskbias[M_];            // 0 or -1e30 per (b, key)

// ---------------------------------------------------------------------------
// Mask expansion, robust to bool-as-int8 or bool-as-int32 serialization.
// ---------------------------------------------------------------------------
__global__ void expand_mask_kernel(const void* __restrict__ pm)
{
    __shared__ int s_byte_mode;
    if (threadIdx.x == 0) s_byte_mode = 0;
    __syncthreads();

    const unsigned* w = (const unsigned*)pm;
    for (int i = threadIdx.x; i < 2048; i += blockDim.x) {
        if (w[i] > 1u) s_byte_mode = 1;   // benign race: same value
    }
    __syncthreads();
    const int byte_mode = s_byte_mode;

    const uint8_t* p8  = (const uint8_t*)pm;
    const int*     p32 = (const int*)pm;
    for (int i = threadIdx.x; i < M_; i += blockDim.x) {
        int m = byte_mode ? (int)p8[i] : p32[i];
        g_maskbias[i] = m ? -1e30f : 0.0f;
    }
}

// ---------------------------------------------------------------------------
// tf32 helpers
// ---------------------------------------------------------------------------
__device__ __forceinline__ uint32_t f2tf(float x) {
    uint32_t r; asm("cvt.rna.tf32.f32 %0, %1;" : "=r"(r) : "f"(x)); return r;
}
__device__ __forceinline__ void mma_tf32(float d[4], const uint32_t a[4],
                                         const uint32_t b[2]) {
    asm volatile("mma.sync.aligned.m16n8k8.row.col.f32.tf32.tf32.f32 "
                 "{%0,%1,%2,%3}, {%4,%5,%6,%7}, {%8,%9}, {%0,%1,%2,%3};"
                 : "+f"(d[0]), "+f"(d[1]), "+f"(d[2]), "+f"(d[3])
                 : "r"(a[0]), "r"(a[1]), "r"(a[2]), "r"(a[3]),
                   "r"(b[0]), "r"(b[1]));
}

// ---------------------------------------------------------------------------
// tf32 GEMM: Cout[M,Nc] = A[M,K] @ W[K,Nc] + bias. 128x128 block, BK=32,
// 8 warps (4x2), warp tile 32x64. Fragment loads conflict-free by pitch:
// As pitch 36 (bank 4g+tig), Ws pitch 136 (bank 8tig+g).
// ---------------------------------------------------------------------------
__global__ __launch_bounds__(256, 2)
void gemm_tf32(const float* __restrict__ A, const float* __restrict__ W,
               const float* __restrict__ bias, float* __restrict__ Cout,
               int K, int Nc)
{
    __shared__ uint32_t Asu[128 * 36];
    __shared__ uint32_t Wsu[32 * 136];
    const int tid = threadIdx.x;
    const int w = tid >> 5, lane = tid & 31;
    const int g = lane >> 2, tig = lane & 3;
    const int wr = w >> 1, wc = w & 1;
    const int bm = blockIdx.y * 128, bn = blockIdx.x * 128;

    float acc[2][8][4];
    #pragma unroll
    for (int mi = 0; mi < 2; mi++)
        #pragma unroll
        for (int n = 0; n < 8; n++)
            #pragma unroll
            for (int j = 0; j < 4; j++) acc[mi][n][j] = 0.f;

    for (int k0 = 0; k0 < K; k0 += 32) {
        __syncthreads();
        #pragma unroll
        for (int i = 0; i < 4; i++) {
            int f = tid + i * 256;
            int r = f >> 3, c = (f & 7) << 2;
            float4 v = *(const float4*)(A + (size_t)(bm + r) * K + k0 + c);
            uint4 u = make_uint4(f2tf(v.x), f2tf(v.y), f2tf(v.z), f2tf(v.w));
            *(uint4*)&Asu[r * 36 + c] = u;
        }
        #pragma unroll
        for (int i = 0; i < 4; i++) {
            int f = tid + i * 256;
            int r = f >> 5, c = (f & 31) << 2;
            float4 v = *(const float4*)(W + (size_t)(k0 + r) * Nc + bn + c);
            uint4 u = make_uint4(f2tf(v.x), f2tf(v.y), f2tf(v.z), f2tf(v.w));
            *(uint4*)&Wsu[r * 136 + c] = u;
        }
        __syncthreads();

        #pragma unroll
        for (int kk = 0; kk < 4; kk++) {
            uint32_t a[2][4];
            #pragma unroll
            for (int mi = 0; mi < 2; mi++) {
                int rb = wr * 32 + mi * 16;
                a[mi][0] = Asu[(rb + g    ) * 36 + tig     + 8 * kk];
                a[mi][1] = Asu[(rb + g + 8) * 36 + tig     + 8 * kk];
                a[mi][2] = Asu[(rb + g    ) * 36 + tig + 4 + 8 * kk];
                a[mi][3] = Asu[(rb + g + 8) * 36 + tig + 4 + 8 * kk];
            }
            #pragma unroll
            for (int n = 0; n < 8; n++) {
                uint32_t bf[2];
                int cb = wc * 64 + n * 8 + g;
                bf[0] = Wsu[(tig     + 8 * kk) * 136 + cb];
                bf[1] = Wsu[(tig + 4 + 8 * kk) * 136 + cb];
                mma_tf32(acc[0][n], a[0], bf);
                mma_tf32(acc[1][n], a[1], bf);
            }
        }
    }

    #pragma unroll
    for (int n = 0; n < 8; n++) {
        int col = bn + wc * 64 + n * 8 + 2 * tig;
        float2 bs = *(const float2*)(bias + col);
        #pragma unroll
        for (int mi = 0; mi < 2; mi++) {
            int r0 = bm + wr * 32 + mi * 16 + g;
            float2 v0 = make_float2(acc[mi][n][0] + bs.x, acc[mi][n][1] + bs.y);
            float2 v1 = make_float2(acc[mi][n][2] + bs.x, acc[mi][n][3] + bs.y);
            *(float2*)(Cout + (size_t)r0 * Nc + col) = v0;
            *(float2*)(Cout + (size_t)(r0 + 8) * Nc + col) = v1;
        }
    }
}

// ---------------------------------------------------------------------------
// tf32 flash attention: 128 q-rows per block, 8 warps, warp owns m16.
// Q fragments register-resident (loaded once). K tile in smem [key][d]
// pitch 68; V tile [key][d] pitch 72; P round-trips smem pitch 68
// (warp-private rows -> only __syncwarp). All mma operand lds conflict-free.
// Softmax, alibi, mask in fp32.
// ---------------------------------------------------------------------------
#define KP 68
#define VP 72
#define PP 68

__global__ __launch_bounds__(256, 2)
void flash_tf32(const float* __restrict__ qkv, const float* __restrict__ alibi,
                float* __restrict__ outp)
{
    extern __shared__ uint32_t smu[];
    uint32_t* Ksu = smu;                    // 64*KP
    uint32_t* Vsu = smu + 64 * KP;          // 64*VP
    uint32_t* Psu = smu + 64 * KP + 64 * VP;// 128*PP

    const int q0 = blockIdx.x * 128;
    const int h = blockIdx.y, b = blockIdx.z;
    const int tid = threadIdx.x;
    const int w = tid >> 5, lane = tid & 31;
    const int g = lane >> 2, tig = lane & 3;
    const int r0 = 16 * w + g;              // block-local q row of c0/c1

    const size_t base = (size_t)b * N_ * C3_ + (size_t)h * D_;

    // Q fragments (held for the whole kernel)
    uint32_t qa[8][4];
    {
        const float* Qr0 = qkv + base + (size_t)(q0 + r0) * C3_;
        const float* Qr1 = Qr0 + 8 * C3_;
        #pragma unroll
        for (int ks = 0; ks < 8; ks++) {
            qa[ks][0] = f2tf(Qr0[tig + 8 * ks]);
            qa[ks][1] = f2tf(Qr1[tig + 8 * ks]);
            qa[ks][2] = f2tf(Qr0[tig + 4 + 8 * ks]);
            qa[ks][3] = f2tf(Qr1[tig + 4 + 8 * ks]);
        }
    }

    float o[8][4];
    #pragma unroll
    for (int n = 0; n < 8; n++)
        #pragma unroll
        for (int j = 0; j < 4; j++) o[n][j] = 0.f;
    float m0 = -1e30f, m1 = -1e30f, l0 = 0.f, l1 = 0.f;

    const float* abase = alibi + ((size_t)(b * H_ + h) * N_ + q0) * N_;
    const float* mbase = g_maskbias + (size_t)b * N_;

    for (int kt = 0; kt < N_ / 64; kt++) {
        const int k0 = kt * 64;
        __syncthreads();
        // Stage K, V tiles (tf32-converted at store)
        #pragma unroll
        for (int i = 0; i < 4; i++) {
            int f = tid + i * 256;
            int key = f >> 4, c4 = (f & 15) << 2;
            const float* kp = qkv + base + C_ + (size_t)(k0 + key) * C3_ + c4;
            float4 kv = *(const float4*)kp;
            float4 vv = *(const float4*)(kp + C_);
            *(uint4*)&Ksu[key * KP + c4] =
                make_uint4(f2tf(kv.x), f2tf(kv.y), f2tf(kv.z), f2tf(kv.w));
            *(uint4*)&Vsu[key * VP + c4] =
                make_uint4(f2tf(vv.x), f2tf(vv.y), f2tf(vv.z), f2tf(vv.w));
        }
        __syncthreads();

        // S = Q @ K^T
        float sc[8][4];
        #pragma unroll
        for (int n = 0; n < 8; n++)
            #pragma unroll
            for (int j = 0; j < 4; j++) sc[n][j] = 0.f;

        #pragma unroll
        for (int ks = 0; ks < 8; ks++) {
            #pragma unroll
            for (int n = 0; n < 8; n++) {
                uint32_t bf[2];
                bf[0] = Ksu[(g + 8 * n) * KP + tig + 8 * ks];
                bf[1] = Ksu[(g + 8 * n) * KP + tig + 4 + 8 * ks];
                mma_tf32(sc[n], qa[ks], bf);
            }
        }

        // scale + alibi + mask
        #pragma unroll
        for (int n = 0; n < 8; n++) {
            float2 mb = *(const float2*)(mbase + k0 + 8 * n + 2 * tig);
            const float* ap0 = abase + (size_t)r0 * N_ + k0 + 8 * n + 2 * tig;
            float2 a0 = *(const float2*)ap0;
            float2 a1 = *(const float2*)(ap0 + 8 * N_);
            sc[n][0] = sc[n][0] * 0.125f + a0.x + mb.x;
            sc[n][1] = sc[n][1] * 0.125f + a0.y + mb.y;
            sc[n][2] = sc[n][2] * 0.125f + a1.x + mb.x;
            sc[n][3] = sc[n][3] * 0.125f + a1.y + mb.y;
        }

        // online softmax (rows r0 via c0/c1, r0+8 via c2/c3)
        float mx0 = -1e30f, mx1 = -1e30f;
        #pragma unroll
        for (int n = 0; n < 8; n++) {
            mx0 = fmaxf(mx0, fmaxf(sc[n][0], sc[n][1]));
            mx1 = fmaxf(mx1, fmaxf(sc[n][2], sc[n][3]));
        }
        mx0 = fmaxf(mx0, __shfl_xor_sync(0xffffffffu, mx0, 1));
        mx0 = fmaxf(mx0, __shfl_xor_sync(0xffffffffu, mx0, 2));
        mx1 = fmaxf(mx1, __shfl_xor_sync(0xffffffffu, mx1, 1));
        mx1 = fmaxf(mx1, __shfl_xor_sync(0xffffffffu, mx1, 2));
        float mn0 = fmaxf(m0, mx0), mn1 = fmaxf(m1, mx1);
        float f0 = __expf(m0 - mn0), f1 = __expf(m1 - mn1);
        m0 = mn0; m1 = mn1;

        float rs0 = 0.f, rs1 = 0.f;
        #pragma unroll
        for (int n = 0; n < 8; n++) {
            sc[n][0] = __expf(sc[n][0] - mn0);
            sc[n][1] = __expf(sc[n][1] - mn0);
            sc[n][2] = __expf(sc[n][2] - mn1);
            sc[n][3] = __expf(sc[n][3] - mn1);
            rs0 += sc[n][0] + sc[n][1];
            rs1 += sc[n][2] + sc[n][3];
        }
        rs0 += __shfl_xor_sync(0xffffffffu, rs0, 1);
        rs0 += __shfl_xor_sync(0xffffffffu, rs0, 2);
        rs1 += __shfl_xor_sync(0xffffffffu, rs1, 1);
        rs1 += __shfl_xor_sync(0xffffffffu, rs1, 2);
        l0 = l0 * f0 + rs0;
        l1 = l1 * f1 + rs1;
        #pragma unroll
        for (int n = 0; n < 8; n++) {
            o[n][0] *= f0; o[n][1] *= f0;
            o[n][2] *= f1; o[n][3] *= f1;
        }

        // store P fragments (tf32 bits) — warp-private rows
        {
            uint32_t* Pr0 = Psu + (size_t)r0 * PP + 2 * tig;
            uint32_t* Pr1 = Pr0 + 8 * PP;
            #pragma unroll
            for (int n = 0; n < 8; n++) {
                *(uint2*)(Pr0 + 8 * n) = make_uint2(f2tf(sc[n][0]), f2tf(sc[n][1]));
                *(uint2*)(Pr1 + 8 * n) = make_uint2(f2tf(sc[n][2]), f2tf(sc[n][3]));
            }
        }
        __syncwarp();

        // O += P @ V
        #pragma unroll
        for (int ks = 0; ks < 8; ks++) {
            uint32_t pa[4];
            pa[0] = Psu[(16 * w + g    ) * PP + tig     + 8 * ks];
            pa[1] = Psu[(16 * w + g + 8) * PP + tig     + 8 * ks];
            pa[2] = Psu[(16 * w + g    ) * PP + tig + 4 + 8 * ks];
            pa[3] = Psu[(16 * w + g + 8) * PP + tig + 4 + 8 * ks];
            #pragma unroll
            for (int n = 0; n < 8; n++) {
                uint32_t vb[2];
                vb[0] = Vsu[(tig     + 8 * ks) * VP + g + 8 * n];
                vb[1] = Vsu[(tig + 4 + 8 * ks) * VP + g + 8 * n];
                mma_tf32(o[n], pa, vb);
            }
        }
    }

    // epilogue: normalize, write [B*N, C] at column h*64
    float i0 = 1.f / l0, i1 = 1.f / l1;
    float* or0 = outp + ((size_t)b * N_ + q0 + r0) * C_ + h * D_ + 2 * tig;
    float* or1 = or0 + 8 * C_;
    #pragma unroll
    for (int n = 0; n < 8; n++) {
        *(float2*)(or0 + 8 * n) = make_float2(o[n][0] * i0, o[n][1] * i0);
        *(float2*)(or1 + 8 * n) = make_float2(o[n][2] * i1, o[n][3] * i1);
    }
}

// ---------------------------------------------------------------------------
extern "C" void kernel_launch(void* const* d_in, const int* in_sizes, int n_in,
                              void* d_out, int out_size)
{
    const float* x      = (const float*)d_in[0];
    const void*  pm     = d_in[1];
    const float* alibi  = (const float*)d_in[2];
    const float* qkv_w  = (const float*)d_in[3];
    const float* qkv_b  = (const float*)d_in[4];
    const float* proj_w = (const float*)d_in[5];
    const float* proj_b = (const float*)d_in[6];
    float* out = (float*)d_out;

    float *qkv, *att;
    cudaGetSymbolAddress((void**)&qkv, g_qkv);
    cudaGetSymbolAddress((void**)&att, g_att);

    const int FLASH_SMEM = (64 * KP + 64 * VP + 128 * PP) * 4;  // 70656 B
    cudaFuncSetAttribute(flash_tf32,
                         cudaFuncAttributeMaxDynamicSharedMemorySize, FLASH_SMEM);

    // 0) expand padding mask (dtype-robust)
    expand_mask_kernel<<<1, 1024>>>(pm);

    // 1) qkv = x @ qkv_w + qkv_b           [8192, 2304]
    gemm_tf32<<<dim3(C3_ / 128, M_ / 128), 256>>>(x, qkv_w, qkv_b, qkv, C_, C3_);

    // 2) flash attention (tf32 mma)        -> g_att
    flash_tf32<<<dim3(N_ / 128, H_, B_), 256, FLASH_SMEM>>>(qkv, alibi, att);

    // 3) out = att @ proj_w + proj_b       [8192, 768]
    gemm_tf32<<<dim3(C_ / 128, M_ / 128), 256>>>(att, proj_w, proj_b, out, C_, C_);
}

// round 4
// speedup vs baseline: 2.9610x; 1.0017x over previous
#include <cuda_runtime.h>
#include <cstdint>

#define B_  4
#define N_  2048
#define C_  768
#define H_  12
#define D_  64
#define C3_ 2304
#define M_  (B_ * N_)   // 8192

// Scratch (device globals — no allocation allowed in kernel_launch)
__device__ float g_qkv[(size_t)M_ * C3_];   // [B*N, 3C]
__device__ float g_att[(size_t)M_ * C_];    // [B*N, C]
__device__ float g_maskbias[M_];            // 0 or -1e30 per (b, key)

// ---------------------------------------------------------------------------
// Mask expansion, robust to bool-as-int8 or bool-as-int32 serialization.
// ---------------------------------------------------------------------------
__global__ void expand_mask_kernel(const void* __restrict__ pm)
{
    __shared__ int s_byte_mode;
    if (threadIdx.x == 0) s_byte_mode = 0;
    __syncthreads();

    const unsigned* w = (const unsigned*)pm;
    for (int i = threadIdx.x; i < 2048; i += blockDim.x) {
        if (w[i] > 1u) s_byte_mode = 1;   // benign race: same value
    }
    __syncthreads();
    const int byte_mode = s_byte_mode;

    const uint8_t* p8  = (const uint8_t*)pm;
    const int*     p32 = (const int*)pm;
    for (int i = threadIdx.x; i < M_; i += blockDim.x) {
        int m = byte_mode ? (int)p8[i] : p32[i];
        g_maskbias[i] = m ? -1e30f : 0.0f;
    }
}

// ---------------------------------------------------------------------------
// tf32 helpers
// ---------------------------------------------------------------------------
__device__ __forceinline__ uint32_t f2tf(float x) {
    uint32_t r; asm("cvt.rna.tf32.f32 %0, %1;" : "=r"(r) : "f"(x)); return r;
}
__device__ __forceinline__ void mma_tf32(float d[4], const uint32_t a[4],
                                         const uint32_t b[2]) {
    asm volatile("mma.sync.aligned.m16n8k8.row.col.f32.tf32.tf32.f32 "
                 "{%0,%1,%2,%3}, {%4,%5,%6,%7}, {%8,%9}, {%0,%1,%2,%3};"
                 : "+f"(d[0]), "+f"(d[1]), "+f"(d[2]), "+f"(d[3])
                 : "r"(a[0]), "r"(a[1]), "r"(a[2]), "r"(a[3]),
                   "r"(b[0]), "r"(b[1]));
}

// ---------------------------------------------------------------------------
// tf32 GEMM: Cout[M,Nc] = A[M,K] @ W[K,Nc] + bias. 128x128 block, BK=32,
// 8 warps (4x2), warp tile 32x64. Fragment loads conflict-free by pitch:
// As pitch 36 (bank 4g+tig), Ws pitch 136 (bank 8tig+g).
// ---------------------------------------------------------------------------
__global__ __launch_bounds__(256, 2)
void gemm_tf32(const float* __restrict__ A, const float* __restrict__ W,
               const float* __restrict__ bias, float* __restrict__ Cout,
               int K, int Nc)
{
    __shared__ uint32_t Asu[128 * 36];
    __shared__ uint32_t Wsu[32 * 136];
    const int tid = threadIdx.x;
    const int w = tid >> 5, lane = tid & 31;
    const int g = lane >> 2, tig = lane & 3;
    const int wr = w >> 1, wc = w & 1;
    const int bm = blockIdx.y * 128, bn = blockIdx.x * 128;

    float acc[2][8][4];
    #pragma unroll
    for (int mi = 0; mi < 2; mi++)
        #pragma unroll
        for (int n = 0; n < 8; n++)
            #pragma unroll
            for (int j = 0; j < 4; j++) acc[mi][n][j] = 0.f;

    for (int k0 = 0; k0 < K; k0 += 32) {
        __syncthreads();
        #pragma unroll
        for (int i = 0; i < 4; i++) {
            int f = tid + i * 256;
            int r = f >> 3, c = (f & 7) << 2;
            float4 v = *(const float4*)(A + (size_t)(bm + r) * K + k0 + c);
            uint4 u = make_uint4(f2tf(v.x), f2tf(v.y), f2tf(v.z), f2tf(v.w));
            *(uint4*)&Asu[r * 36 + c] = u;
        }
        #pragma unroll
        for (int i = 0; i < 4; i++) {
            int f = tid + i * 256;
            int r = f >> 5, c = (f & 31) << 2;
            float4 v = *(const float4*)(W + (size_t)(k0 + r) * Nc + bn + c);
            uint4 u = make_uint4(f2tf(v.x), f2tf(v.y), f2tf(v.z), f2tf(v.w));
            *(uint4*)&Wsu[r * 136 + c] = u;
        }
        __syncthreads();

        #pragma unroll
        for (int kk = 0; kk < 4; kk++) {
            uint32_t a[2][4];
            #pragma unroll
            for (int mi = 0; mi < 2; mi++) {
                int rb = wr * 32 + mi * 16;
                a[mi][0] = Asu[(rb + g    ) * 36 + tig     + 8 * kk];
                a[mi][1] = Asu[(rb + g + 8) * 36 + tig     + 8 * kk];
                a[mi][2] = Asu[(rb + g    ) * 36 + tig + 4 + 8 * kk];
                a[mi][3] = Asu[(rb + g + 8) * 36 + tig + 4 + 8 * kk];
            }
            #pragma unroll
            for (int n = 0; n < 8; n++) {
                uint32_t bf[2];
                int cb = wc * 64 + n * 8 + g;
                bf[0] = Wsu[(tig     + 8 * kk) * 136 + cb];
                bf[1] = Wsu[(tig + 4 + 8 * kk) * 136 + cb];
                mma_tf32(acc[0][n], a[0], bf);
                mma_tf32(acc[1][n], a[1], bf);
            }
        }
    }

    #pragma unroll
    for (int n = 0; n < 8; n++) {
        int col = bn + wc * 64 + n * 8 + 2 * tig;
        float2 bs = *(const float2*)(bias + col);
        #pragma unroll
        for (int mi = 0; mi < 2; mi++) {
            int r0 = bm + wr * 32 + mi * 16 + g;
            float2 v0 = make_float2(acc[mi][n][0] + bs.x, acc[mi][n][1] + bs.y);
            float2 v1 = make_float2(acc[mi][n][2] + bs.x, acc[mi][n][3] + bs.y);
            *(float2*)(Cout + (size_t)r0 * Nc + col) = v0;
            *(float2*)(Cout + (size_t)(r0 + 8) * Nc + col) = v1;
        }
    }
}

// ---------------------------------------------------------------------------
// tf32 flash attention: 128 q-rows per block, 8 warps, warp owns m16.
// Q fragments register-resident (loaded once). K tile in smem [key][d]
// pitch 68; V tile [key][d] pitch 72; P round-trips smem pitch 68
// (warp-private rows -> only __syncwarp). All mma operand lds conflict-free.
// Softmax, alibi, mask in fp32.
// ---------------------------------------------------------------------------
#define KP 68
#define VP 72
#define PP 68

__global__ __launch_bounds__(256, 2)
void flash_tf32(const float* __restrict__ qkv, const float* __restrict__ alibi,
                float* __restrict__ outp)
{
    extern __shared__ uint32_t smu[];
    uint32_t* Ksu = smu;                    // 64*KP
    uint32_t* Vsu = smu + 64 * KP;          // 64*VP
    uint32_t* Psu = smu + 64 * KP + 64 * VP;// 128*PP

    const int q0 = blockIdx.x * 128;
    const int h = blockIdx.y, b = blockIdx.z;
    const int tid = threadIdx.x;
    const int w = tid >> 5, lane = tid & 31;
    const int g = lane >> 2, tig = lane & 3;
    const int r0 = 16 * w + g;              // block-local q row of c0/c1

    const size_t base = (size_t)b * N_ * C3_ + (size_t)h * D_;

    // Q fragments (held for the whole kernel)
    uint32_t qa[8][4];
    {
        const float* Qr0 = qkv + base + (size_t)(q0 + r0) * C3_;
        const float* Qr1 = Qr0 + 8 * C3_;
        #pragma unroll
        for (int ks = 0; ks < 8; ks++) {
            qa[ks][0] = f2tf(Qr0[tig + 8 * ks]);
            qa[ks][1] = f2tf(Qr1[tig + 8 * ks]);
            qa[ks][2] = f2tf(Qr0[tig + 4 + 8 * ks]);
            qa[ks][3] = f2tf(Qr1[tig + 4 + 8 * ks]);
        }
    }

    float o[8][4];
    #pragma unroll
    for (int n = 0; n < 8; n++)
        #pragma unroll
        for (int j = 0; j < 4; j++) o[n][j] = 0.f;
    float m0 = -1e30f, m1 = -1e30f, l0 = 0.f, l1 = 0.f;

    const float* abase = alibi + ((size_t)(b * H_ + h) * N_ + q0) * N_;
    const float* mbase = g_maskbias + (size_t)b * N_;

    for (int kt = 0; kt < N_ / 64; kt++) {
        const int k0 = kt * 64;
        __syncthreads();
        // Stage K, V tiles (tf32-converted at store)
        #pragma unroll
        for (int i = 0; i < 4; i++) {
            int f = tid + i * 256;
            int key = f >> 4, c4 = (f & 15) << 2;
            const float* kp = qkv + base + C_ + (size_t)(k0 + key) * C3_ + c4;
            float4 kv = *(const float4*)kp;
            float4 vv = *(const float4*)(kp + C_);
            *(uint4*)&Ksu[key * KP + c4] =
                make_uint4(f2tf(kv.x), f2tf(kv.y), f2tf(kv.z), f2tf(kv.w));
            *(uint4*)&Vsu[key * VP + c4] =
                make_uint4(f2tf(vv.x), f2tf(vv.y), f2tf(vv.z), f2tf(vv.w));
        }
        __syncthreads();

        // S = Q @ K^T
        float sc[8][4];
        #pragma unroll
        for (int n = 0; n < 8; n++)
            #pragma unroll
            for (int j = 0; j < 4; j++) sc[n][j] = 0.f;

        #pragma unroll
        for (int ks = 0; ks < 8; ks++) {
            #pragma unroll
            for (int n = 0; n < 8; n++) {
                uint32_t bf[2];
                bf[0] = Ksu[(g + 8 * n) * KP + tig + 8 * ks];
                bf[1] = Ksu[(g + 8 * n) * KP + tig + 4 + 8 * ks];
                mma_tf32(sc[n], qa[ks], bf);
            }
        }

        // scale + alibi + mask
        #pragma unroll
        for (int n = 0; n < 8; n++) {
            float2 mb = *(const float2*)(mbase + k0 + 8 * n + 2 * tig);
            const float* ap0 = abase + (size_t)r0 * N_ + k0 + 8 * n + 2 * tig;
            float2 a0 = *(const float2*)ap0;
            float2 a1 = *(const float2*)(ap0 + 8 * N_);
            sc[n][0] = sc[n][0] * 0.125f + a0.x + mb.x;
            sc[n][1] = sc[n][1] * 0.125f + a0.y + mb.y;
            sc[n][2] = sc[n][2] * 0.125f + a1.x + mb.x;
            sc[n][3] = sc[n][3] * 0.125f + a1.y + mb.y;
        }

        // online softmax (rows r0 via c0/c1, r0+8 via c2/c3)
        float mx0 = -1e30f, mx1 = -1e30f;
        #pragma unroll
        for (int n = 0; n < 8; n++) {
            mx0 = fmaxf(mx0, fmaxf(sc[n][0], sc[n][1]));
            mx1 = fmaxf(mx1, fmaxf(sc[n][2], sc[n][3]));
        }
        mx0 = fmaxf(mx0, __shfl_xor_sync(0xffffffffu, mx0, 1));
        mx0 = fmaxf(mx0, __shfl_xor_sync(0xffffffffu, mx0, 2));
        mx1 = fmaxf(mx1, __shfl_xor_sync(0xffffffffu, mx1, 1));
        mx1 = fmaxf(mx1, __shfl_xor_sync(0xffffffffu, mx1, 2));
        float mn0 = fmaxf(m0, mx0), mn1 = fmaxf(m1, mx1);
        float f0 = __expf(m0 - mn0), f1 = __expf(m1 - mn1);
        m0 = mn0; m1 = mn1;

        float rs0 = 0.f, rs1 = 0.f;
        #pragma unroll
        for (int n = 0; n < 8; n++) {
            sc[n][0] = __expf(sc[n][0] - mn0);
            sc[n][1] = __expf(sc[n][1] - mn0);
            sc[n][2] = __expf(sc[n][2] - mn1);
            sc[n][3] = __expf(sc[n][3] - mn1);
            rs0 += sc[n][0] + sc[n][1];
            rs1 += sc[n][2] + sc[n][3];
        }
        rs0 += __shfl_xor_sync(0xffffffffu, rs0, 1);
        rs0 += __shfl_xor_sync(0xffffffffu, rs0, 2);
        rs1 += __shfl_xor_sync(0xffffffffu, rs1, 1);
        rs1 += __shfl_xor_sync(0xffffffffu, rs1, 2);
        l0 = l0 * f0 + rs0;
        l1 = l1 * f1 + rs1;
        #pragma unroll
        for (int n = 0; n < 8; n++) {
            o[n][0] *= f0; o[n][1] *= f0;
            o[n][2] *= f1; o[n][3] *= f1;
        }

        // store P fragments (tf32 bits) — warp-private rows
        {
            uint32_t* Pr0 = Psu + (size_t)r0 * PP + 2 * tig;
            uint32_t* Pr1 = Pr0 + 8 * PP;
            #pragma unroll
            for (int n = 0; n < 8; n++) {
                *(uint2*)(Pr0 + 8 * n) = make_uint2(f2tf(sc[n][0]), f2tf(sc[n][1]));
                *(uint2*)(Pr1 + 8 * n) = make_uint2(f2tf(sc[n][2]), f2tf(sc[n][3]));
            }
        }
        __syncwarp();

        // O += P @ V
        #pragma unroll
        for (int ks = 0; ks < 8; ks++) {
            uint32_t pa[4];
            pa[0] = Psu[(16 * w + g    ) * PP + tig     + 8 * ks];
            pa[1] = Psu[(16 * w + g + 8) * PP + tig     + 8 * ks];
            pa[2] = Psu[(16 * w + g    ) * PP + tig + 4 + 8 * ks];
            pa[3] = Psu[(16 * w + g + 8) * PP + tig + 4 + 8 * ks];
            #pragma unroll
            for (int n = 0; n < 8; n++) {
                uint32_t vb[2];
                vb[0] = Vsu[(tig     + 8 * ks) * VP + g + 8 * n];
                vb[1] = Vsu[(tig + 4 + 8 * ks) * VP + g + 8 * n];
                mma_tf32(o[n], pa, vb);
            }
        }
    }

    // epilogue: normalize, write [B*N, C] at column h*64
    float i0 = 1.f / l0, i1 = 1.f / l1;
    float* or0 = outp + ((size_t)b * N_ + q0 + r0) * C_ + h * D_ + 2 * tig;
    float* or1 = or0 + 8 * C_;
    #pragma unroll
    for (int n = 0; n < 8; n++) {
        *(float2*)(or0 + 8 * n) = make_float2(o[n][0] * i0, o[n][1] * i0);
        *(float2*)(or1 + 8 * n) = make_float2(o[n][2] * i1, o[n][3] * i1);
    }
}

// ---------------------------------------------------------------------------
extern "C" void kernel_launch(void* const* d_in, const int* in_sizes, int n_in,
                              void* d_out, int out_size)
{
    const float* x      = (const float*)d_in[0];
    const void*  pm     = d_in[1];
    const float* alibi  = (const float*)d_in[2];
    const float* qkv_w  = (const float*)d_in[3];
    const float* qkv_b  = (const float*)d_in[4];
    const float* proj_w = (const float*)d_in[5];
    const float* proj_b = (const float*)d_in[6];
    float* out = (float*)d_out;

    float *qkv, *att;
    cudaGetSymbolAddress((void**)&qkv, g_qkv);
    cudaGetSymbolAddress((void**)&att, g_att);

    const int FLASH_SMEM = (64 * KP + 64 * VP + 128 * PP) * 4;  // 70656 B
    cudaFuncSetAttribute(flash_tf32,
                         cudaFuncAttributeMaxDynamicSharedMemorySize, FLASH_SMEM);

    // 0) expand padding mask (dtype-robust)
    expand_mask_kernel<<<1, 1024>>>(pm);

    // 1) qkv = x @ qkv_w + qkv_b           [8192, 2304]
    gemm_tf32<<<dim3(C3_ / 128, M_ / 128), 256>>>(x, qkv_w, qkv_b, qkv, C_, C3_);

    // 2) flash attention (tf32 mma)        -> g_att
    flash_tf32<<<dim3(N_ / 128, H_, B_), 256, FLASH_SMEM>>>(qkv, alibi, att);

    // 3) out = att @ proj_w + proj_b       [8192, 768]
    gemm_tf32<<<dim3(C_ / 128, M_ / 128), 256>>>(att, proj_w, proj_b, out, C_, C_);
}

// round 6
// speedup vs baseline: 5.5317x; 1.8682x over previous
#include <cuda_runtime.h>
#include <cuda_fp16.h>
#include <cstdint>

#define B_  4
#define N_  2048
#define C_  768
#define H_  12
#define D_  64
#define C3_ 2304
#define M_  (B_ * N_)   // 8192

__device__ __half g_x_h[(size_t)M_ * C_];
__device__ __half g_qkvw_h[(size_t)C_ * C3_];
__device__ __half g_projw_h[(size_t)C_ * C_];
__device__ __half g_qkv_h[(size_t)M_ * C3_];
__device__ __half g_att_h[(size_t)M_ * C_];
__device__ float  g_maskbias[M_];

// ---------------- helpers ----------------
__device__ __forceinline__ uint32_t smaddr(const void* p) {
    return (uint32_t)__cvta_generic_to_shared(p);
}
__device__ __forceinline__ void cp16(uint32_t dst, const void* src) {
    asm volatile("cp.async.cg.shared.global [%0], [%1], 16;" :: "r"(dst), "l"(src));
}
__device__ __forceinline__ void cp_commit() { asm volatile("cp.async.commit_group;"); }
template<int Nw> __device__ __forceinline__ void cp_wait() {
    asm volatile("cp.async.wait_group %0;" :: "n"(Nw));
}
__device__ __forceinline__ void ldsm4(uint32_t a, uint32_t& r0, uint32_t& r1,
                                      uint32_t& r2, uint32_t& r3) {
    asm volatile("ldmatrix.sync.aligned.m8n8.x4.shared.b16 {%0,%1,%2,%3}, [%4];"
                 : "=r"(r0), "=r"(r1), "=r"(r2), "=r"(r3) : "r"(a));
}
__device__ __forceinline__ void ldsm4t(uint32_t a, uint32_t& r0, uint32_t& r1,
                                       uint32_t& r2, uint32_t& r3) {
    asm volatile("ldmatrix.sync.aligned.m8n8.x4.trans.shared.b16 {%0,%1,%2,%3}, [%4];"
                 : "=r"(r0), "=r"(r1), "=r"(r2), "=r"(r3) : "r"(a));
}
__device__ __forceinline__ void mma_f16(float d[4], const uint32_t a[4],
                                        uint32_t b0, uint32_t b1) {
    asm volatile("mma.sync.aligned.m16n8k16.row.col.f32.f16.f16.f32 "
                 "{%0,%1,%2,%3}, {%4,%5,%6,%7}, {%8,%9}, {%0,%1,%2,%3};"
                 : "+f"(d[0]), "+f"(d[1]), "+f"(d[2]), "+f"(d[3])
                 : "r"(a[0]), "r"(a[1]), "r"(a[2]), "r"(a[3]), "r"(b0), "r"(b1));
}
// pack two fp32 -> one u32 holding f16x2 (lo = x, hi = y)
__device__ __forceinline__ uint32_t pack_f16x2(float x, float y) {
    uint32_t r;
    asm("cvt.rn.f16x2.f32 %0, %1, %2;" : "=r"(r) : "f"(y), "f"(x));
    return r;
}

// ---------------- mask expansion (dtype-robust) ----------------
__global__ void expand_mask_kernel(const void* __restrict__ pm)
{
    __shared__ int s_byte_mode;
    if (threadIdx.x == 0) s_byte_mode = 0;
    __syncthreads();
    const unsigned* w = (const unsigned*)pm;
    for (int i = threadIdx.x; i < 2048; i += blockDim.x)
        if (w[i] > 1u) s_byte_mode = 1;
    __syncthreads();
    const int byte_mode = s_byte_mode;
    const uint8_t* p8  = (const uint8_t*)pm;
    const int*     p32 = (const int*)pm;
    for (int i = threadIdx.x; i < M_; i += blockDim.x) {
        int m = byte_mode ? (int)p8[i] : p32[i];
        g_maskbias[i] = m ? -1e30f : 0.0f;
    }
}

// ---------------- fp32 -> fp16 convert ----------------
__global__ void f2h_kernel(const float4* __restrict__ src,
                           __half2* __restrict__ dst, int n4)
{
    int i = blockIdx.x * blockDim.x + threadIdx.x;
    if (i < n4) {
        float4 v = src[i];
        dst[2 * i]     = __floats2half2_rn(v.x, v.y);
        dst[2 * i + 1] = __floats2half2_rn(v.z, v.w);
    }
}

// ---------------------------------------------------------------------------
// fp16 GEMM: Cout = A[M,K]@W[K,Nc] + bias. CTA 128x128, BK=32, 8 warps (4x2),
// warp 32x64. cp.async double-buffered. A: ldmatrix.x4; W: ldmatrix.x4.trans.
// ---------------------------------------------------------------------------
#define AP2 20   // u32 pitch A rows (16 data + 4 pad)  -> 80 B
#define WP2 68   // u32 pitch W rows (64 data + 4 pad)  -> 272 B

template<int OUTH>
__global__ __launch_bounds__(256, 2)
void gemm_h(const __half* __restrict__ A, const __half* __restrict__ W,
            const float* __restrict__ bias, void* __restrict__ Cout,
            int K, int Nc)
{
    __shared__ uint32_t sA[2][128 * AP2];
    __shared__ uint32_t sW[2][32 * WP2];
    const int tid = threadIdx.x, w = tid >> 5, lane = tid & 31;
    const int g = lane >> 2, tig = lane & 3;
    const int wr = w >> 1, wc = w & 1;
    const int bm = blockIdx.y * 128, bn = blockIdx.x * 128;
    const int NI = K / 32;
    const uint32_t sAb[2] = { smaddr(&sA[0][0]), smaddr(&sA[1][0]) };
    const uint32_t sWb[2] = { smaddr(&sW[0][0]), smaddr(&sW[1][0]) };

    auto stage = [&](int buf, int k0) {
        #pragma unroll
        for (int i = 0; i < 2; i++) {
            int c = tid + i * 256, r = c >> 2, cb = c & 3;
            cp16(sAb[buf] + r * (AP2 * 4) + cb * 16,
                 A + (size_t)(bm + r) * K + k0 + cb * 8);
        }
        #pragma unroll
        for (int i = 0; i < 2; i++) {
            int c = tid + i * 256, r = c >> 4, cb = c & 15;
            cp16(sWb[buf] + r * (WP2 * 4) + cb * 16,
                 W + (size_t)(k0 + r) * Nc + bn + cb * 8);
        }
    };

    float acc[2][8][4];
    #pragma unroll
    for (int mi = 0; mi < 2; mi++)
        #pragma unroll
        for (int n = 0; n < 8; n++)
            #pragma unroll
            for (int j = 0; j < 4; j++) acc[mi][n][j] = 0.f;

    stage(0, 0); cp_commit();

    for (int it = 0; it < NI; it++) {
        const int cur = it & 1;
        if (it + 1 < NI) { stage(1 - cur, (it + 1) * 32); cp_commit(); cp_wait<1>(); }
        else             { cp_wait<0>(); }
        __syncthreads();

        #pragma unroll
        for (int s = 0; s < 2; s++) {
            uint32_t af[2][4];
            #pragma unroll
            for (int mi = 0; mi < 2; mi++) {
                uint32_t a = sAb[cur]
                    + (uint32_t)(wr * 32 + mi * 16 + (lane & 15)) * (AP2 * 4)
                    + s * 32 + (lane >> 4) * 16;
                ldsm4(a, af[mi][0], af[mi][1], af[mi][2], af[mi][3]);
            }
            #pragma unroll
            for (int njp = 0; njp < 4; njp++) {
                uint32_t b0, b1, b2, b3;
                uint32_t a = sWb[cur]
                    + (uint32_t)(16 * s + (lane & 15)) * (WP2 * 4)
                    + wc * 128 + njp * 32 + (lane >> 4) * 16;
                ldsm4t(a, b0, b1, b2, b3);
                mma_f16(acc[0][2 * njp],     af[0], b0, b1);
                mma_f16(acc[1][2 * njp],     af[1], b0, b1);
                mma_f16(acc[0][2 * njp + 1], af[0], b2, b3);
                mma_f16(acc[1][2 * njp + 1], af[1], b2, b3);
            }
        }
        __syncthreads();
    }

    #pragma unroll
    for (int n = 0; n < 8; n++) {
        int col = bn + wc * 64 + n * 8 + 2 * tig;
        float2 bs = *(const float2*)(bias + col);
        #pragma unroll
        for (int mi = 0; mi < 2; mi++) {
            size_t r = (size_t)(bm + wr * 32 + mi * 16 + g);
            if (OUTH) {
                __half* Ch = (__half*)Cout;
                *(uint32_t*)(Ch + r * Nc + col) =
                    pack_f16x2(acc[mi][n][0] + bs.x, acc[mi][n][1] + bs.y);
                *(uint32_t*)(Ch + (r + 8) * Nc + col) =
                    pack_f16x2(acc[mi][n][2] + bs.x, acc[mi][n][3] + bs.y);
            } else {
                float* Cf = (float*)Cout;
                *(float2*)(Cf + r * Nc + col) =
                    make_float2(acc[mi][n][0] + bs.x, acc[mi][n][1] + bs.y);
                *(float2*)(Cf + (r + 8) * Nc + col) =
                    make_float2(acc[mi][n][2] + bs.x, acc[mi][n][3] + bs.y);
            }
        }
    }
}

// ---------------------------------------------------------------------------
// fp16 flash: 128 q-rows/block, 8 warps (warp owns m16). K/V cp.async
// double-buffered (pitch 36 u32 = 144B). Q frags register-resident;
// P packed fp16 in smem, reloaded via ldmatrix. Softmax fp32.
// ---------------------------------------------------------------------------
#define KVP 36

__global__ __launch_bounds__(256, 2)
void flash_h(const __half* __restrict__ qkv, const float* __restrict__ alibi,
             __half* __restrict__ outp)
{
    extern __shared__ uint32_t smu[];
    const int q0 = blockIdx.x * 128;
    const int h = blockIdx.y, b = blockIdx.z;
    const int tid = threadIdx.x, w = tid >> 5, lane = tid & 31;
    const int g = lane >> 2, tig = lane & 3;
    const int r0 = 16 * w + g;

    const uint32_t sbase = smaddr(smu);
    const uint32_t Kb[2] = { sbase,                  sbase + 2 * 64 * KVP * 4 };
    const uint32_t Vb[2] = { sbase + 64 * KVP * 4,   sbase + 3 * 64 * KVP * 4 };
    const uint32_t Pb    = sbase + 4 * 64 * KVP * 4;

    const size_t hbase = (size_t)b * N_ * C3_ + (size_t)h * D_;
    const __half* Kg = qkv + hbase + C_;
    const __half* Vg = qkv + hbase + 2 * C_;

    // Q fragments (held all kernel)
    uint32_t qa[4][4];
    {
        const uint32_t* Qr0 = (const uint32_t*)(qkv + hbase + (size_t)(q0 + r0) * C3_);
        const uint32_t* Qr1 = Qr0 + 8 * (C3_ / 2);
        #pragma unroll
        for (int s = 0; s < 4; s++) {
            qa[s][0] = Qr0[tig + 8 * s];
            qa[s][1] = Qr1[tig + 8 * s];
            qa[s][2] = Qr0[tig + 4 + 8 * s];
            qa[s][3] = Qr1[tig + 4 + 8 * s];
        }
    }

    auto stageKV = [&](int buf, int k0) {
        #pragma unroll
        for (int i = 0; i < 2; i++) {
            int c = tid + i * 256, r = c >> 3, cb = c & 7;
            cp16(Kb[buf] + r * (KVP * 4) + cb * 16, Kg + (size_t)(k0 + r) * C3_ + cb * 8);
        }
        #pragma unroll
        for (int i = 0; i < 2; i++) {
            int c = tid + i * 256, r = c >> 3, cb = c & 7;
            cp16(Vb[buf] + r * (KVP * 4) + cb * 16, Vg + (size_t)(k0 + r) * C3_ + cb * 8);
        }
    };

    float o[8][4];
    #pragma unroll
    for (int n = 0; n < 8; n++)
        #pragma unroll
        for (int j = 0; j < 4; j++) o[n][j] = 0.f;
    float m0 = -1e30f, m1 = -1e30f, l0 = 0.f, l1 = 0.f;

    const float* abase = alibi + ((size_t)(b * H_ + h) * N_ + q0) * N_;
    const float* mbase = g_maskbias + (size_t)b * N_;

    stageKV(0, 0); cp_commit();

    for (int kt = 0; kt < N_ / 64; kt++) {
        const int k0 = kt * 64;
        const int cur = kt & 1;
        if (kt + 1 < N_ / 64) { stageKV(1 - cur, (kt + 1) * 64); cp_commit(); cp_wait<1>(); }
        else                  { cp_wait<0>(); }
        __syncthreads();

        // S = Q @ K^T
        float sc[8][4];
        #pragma unroll
        for (int n = 0; n < 8; n++)
            #pragma unroll
            for (int j = 0; j < 4; j++) sc[n][j] = 0.f;

        #pragma unroll
        for (int s = 0; s < 4; s++) {
            #pragma unroll
            for (int nb = 0; nb < 8; nb += 2) {
                uint32_t b0, b1, b2, b3;
                uint32_t a = Kb[cur]
                    + (uint32_t)(8 * nb + (lane & 7) + 8 * (lane >> 4)) * (KVP * 4)
                    + s * 32 + ((lane >> 3) & 1) * 16;
                ldsm4(a, b0, b1, b2, b3);
                mma_f16(sc[nb],     qa[s], b0, b1);
                mma_f16(sc[nb + 1], qa[s], b2, b3);
            }
        }

        // scale + alibi + mask
        #pragma unroll
        for (int n = 0; n < 8; n++) {
            float2 mb = *(const float2*)(mbase + k0 + 8 * n + 2 * tig);
            const float* ap0 = abase + (size_t)r0 * N_ + k0 + 8 * n + 2 * tig;
            float2 a0 = *(const float2*)ap0;
            float2 a1 = *(const float2*)(ap0 + 8 * N_);
            sc[n][0] = sc[n][0] * 0.125f + a0.x + mb.x;
            sc[n][1] = sc[n][1] * 0.125f + a0.y + mb.y;
            sc[n][2] = sc[n][2] * 0.125f + a1.x + mb.x;
            sc[n][3] = sc[n][3] * 0.125f + a1.y + mb.y;
        }

        // online softmax
        float mx0 = -1e30f, mx1 = -1e30f;
        #pragma unroll
        for (int n = 0; n < 8; n++) {
            mx0 = fmaxf(mx0, fmaxf(sc[n][0], sc[n][1]));
            mx1 = fmaxf(mx1, fmaxf(sc[n][2], sc[n][3]));
        }
        mx0 = fmaxf(mx0, __shfl_xor_sync(0xffffffffu, mx0, 1));
        mx0 = fmaxf(mx0, __shfl_xor_sync(0xffffffffu, mx0, 2));
        mx1 = fmaxf(mx1, __shfl_xor_sync(0xffffffffu, mx1, 1));
        mx1 = fmaxf(mx1, __shfl_xor_sync(0xffffffffu, mx1, 2));
        float mn0 = fmaxf(m0, mx0), mn1 = fmaxf(m1, mx1);
        float f0 = __expf(m0 - mn0), f1 = __expf(m1 - mn1);
        m0 = mn0; m1 = mn1;

        float rs0 = 0.f, rs1 = 0.f;
        #pragma unroll
        for (int n = 0; n < 8; n++) {
            sc[n][0] = __expf(sc[n][0] - mn0);
            sc[n][1] = __expf(sc[n][1] - mn0);
            sc[n][2] = __expf(sc[n][2] - mn1);
            sc[n][3] = __expf(sc[n][3] - mn1);
            rs0 += sc[n][0] + sc[n][1];
            rs1 += sc[n][2] + sc[n][3];
        }
        rs0 += __shfl_xor_sync(0xffffffffu, rs0, 1);
        rs0 += __shfl_xor_sync(0xffffffffu, rs0, 2);
        rs1 += __shfl_xor_sync(0xffffffffu, rs1, 1);
        rs1 += __shfl_xor_sync(0xffffffffu, rs1, 2);
        l0 = l0 * f0 + rs0;
        l1 = l1 * f1 + rs1;
        #pragma unroll
        for (int n = 0; n < 8; n++) {
            o[n][0] *= f0; o[n][1] *= f0;
            o[n][2] *= f1; o[n][3] *= f1;
        }

        // pack P to fp16 smem (warp-private rows)
        {
            uint32_t* Pu = smu + 4 * 64 * KVP;
            uint32_t* Pr0 = Pu + (size_t)r0 * KVP + tig;
            uint32_t* Pr1 = Pr0 + 8 * KVP;
            #pragma unroll
            for (int n = 0; n < 8; n++) {
                Pr0[4 * n] = pack_f16x2(sc[n][0], sc[n][1]);
                Pr1[4 * n] = pack_f16x2(sc[n][2], sc[n][3]);
            }
        }
        __syncwarp();

        // O += P @ V
        #pragma unroll
        for (int s = 0; s < 4; s++) {
            uint32_t pa[4];
            {
                uint32_t a = Pb + (uint32_t)(16 * w + (lane & 15)) * (KVP * 4)
                           + s * 32 + (lane >> 4) * 16;
                ldsm4(a, pa[0], pa[1], pa[2], pa[3]);
            }
            #pragma unroll
            for (int pr = 0; pr < 4; pr++) {
                uint32_t b0, b1, b2, b3;
                uint32_t a = Vb[cur] + (uint32_t)(16 * s + (lane & 15)) * (KVP * 4)
                           + pr * 32 + (lane >> 4) * 16;
                ldsm4t(a, b0, b1, b2, b3);
                mma_f16(o[2 * pr],     pa, b0, b1);
                mma_f16(o[2 * pr + 1], pa, b2, b3);
            }
        }
        __syncthreads();
    }

    // epilogue
    float i0 = 1.f / l0, i1 = 1.f / l1;
    __half* or0 = outp + ((size_t)b * N_ + q0 + r0) * C_ + h * D_ + 2 * tig;
    __half* or1 = or0 + 8 * C_;
    #pragma unroll
    for (int n = 0; n < 8; n++) {
        *(uint32_t*)(or0 + 8 * n) = pack_f16x2(o[n][0] * i0, o[n][1] * i0);
        *(uint32_t*)(or1 + 8 * n) = pack_f16x2(o[n][2] * i1, o[n][3] * i1);
    }
}

// ---------------------------------------------------------------------------
extern "C" void kernel_launch(void* const* d_in, const int* in_sizes, int n_in,
                              void* d_out, int out_size)
{
    const float* x      = (const float*)d_in[0];
    const void*  pm     = d_in[1];
    const float* alibi  = (const float*)d_in[2];
    const float* qkv_w  = (const float*)d_in[3];
    const float* qkv_b  = (const float*)d_in[4];
    const float* proj_w = (const float*)d_in[5];
    const float* proj_b = (const float*)d_in[6];
    float* out = (float*)d_out;

    __half *xh, *qwh, *pwh, *qkvh, *atth;
    cudaGetSymbolAddress((void**)&xh,   g_x_h);
    cudaGetSymbolAddress((void**)&qwh,  g_qkvw_h);
    cudaGetSymbolAddress((void**)&pwh,  g_projw_h);
    cudaGetSymbolAddress((void**)&qkvh, g_qkv_h);
    cudaGetSymbolAddress((void**)&atth, g_att_h);

    const int FLASH_SMEM = (4 * 64 * KVP + 128 * KVP) * 4;  // 55296 B
    cudaFuncSetAttribute(flash_h,
                         cudaFuncAttributeMaxDynamicSharedMemorySize, FLASH_SMEM);

    expand_mask_kernel<<<1, 1024>>>(pm);

    int n4;
    n4 = M_ * C_ / 4;
    f2h_kernel<<<(n4 + 255) / 256, 256>>>((const float4*)x, (__half2*)xh, n4);
    n4 = C_ * C3_ / 4;
    f2h_kernel<<<(n4 + 255) / 256, 256>>>((const float4*)qkv_w, (__half2*)qwh, n4);
    n4 = C_ * C_ / 4;
    f2h_kernel<<<(n4 + 255) / 256, 256>>>((const float4*)proj_w, (__half2*)pwh, n4);

    gemm_h<1><<<dim3(C3_ / 128, M_ / 128), 256>>>(xh, qwh, qkv_b, qkvh, C_, C3_);
    flash_h<<<dim3(N_ / 128, H_, B_), 256, FLASH_SMEM>>>(qkvh, alibi, atth);
    gemm_h<0><<<dim3(C_ / 128, M_ / 128), 256>>>(atth, pwh, proj_b, out, C_, C_);
}